// round 14
// baseline (speedup 1.0000x reference)
#include <cuda_runtime.h>
#include <math.h>

// features: (1, 50, 50, 1024) fp32 NHWC ; boxes: (1, 300, 4) fp32 [y1,x1,y2,x2]
// crop 14x14 bilinear, 2x2 max pool -> out (1, 300, 7, 7, 1024) fp32
// Block = (box, pooled-row py, channel-half). 128 threads, 1 float4 group each.
// NR = distinct rows (2/3/4, block-uniform). Per-task NEAR/FAR x-mode:
//   FAR  (dx>=1): 4 cols {c0,c0+1,c2,c2+1}, R10 branchless path.
//   NEAR (dx<1) : dc in {0,1} for every px -> 3 cols {c0,c0+1,c0+2};
//                 sample1 = hat-weighted sum over the 3 cols (select-free).
// Depth-2 px pipeline keeps ~loads for px+1 in flight while px computes.

#define FH 50
#define FW 50
#define FC 1024
#define NBOX 300
#define CROP 14
#define PO 7
#define C4 (FC / 4)      // 256 float4 channel groups
#define TPB 128
#define ROWS4 (FW * C4)

__device__ __forceinline__ float4 wsum(const float4 tl, const float4 tr,
                                       const float4 bl, const float4 br,
                                       const float a, const float b)
{
    const float aa = 1.0f - a;
    const float bb = 1.0f - b;
    const float w0 = aa * bb, w1 = a * bb, w2 = aa * b, w3 = a * b;
    float4 v;
    v.x = fmaf(w3, br.x, fmaf(w2, bl.x, fmaf(w1, tr.x, w0 * tl.x)));
    v.y = fmaf(w3, br.y, fmaf(w2, bl.y, fmaf(w1, tr.y, w0 * tl.y)));
    v.z = fmaf(w3, br.z, fmaf(w2, bl.z, fmaf(w1, tr.z, w0 * tl.z)));
    v.w = fmaf(w3, br.w, fmaf(w2, bl.w, fmaf(w1, tr.w, w0 * tl.w)));
    return v;
}

__device__ __forceinline__ void max4(float4& m, const float4 v)
{
    m.x = fmaxf(m.x, v.x);
    m.y = fmaxf(m.y, v.y);
    m.z = fmaxf(m.z, v.z);
    m.w = fmaxf(m.w, v.w);
}

// ---------------- FAR path (dx >= 1): unchanged R10 body ----------------

__device__ __forceinline__ void px_cols(const float xbase, const float dx,
                                        const int px,
                                        int coff[4], float& wx0, float& wx1)
{
    const float xs0 = fmaf((float)(2 * px), dx, xbase);
    const float xs1 = xs0 + dx;
    const float xf0 = floorf(xs0), xf1 = floorf(xs1);
    wx0 = xs0 - xf0;
    wx1 = xs1 - xf1;
    const int c0 = min(max((int)xf0, 0), FW - 2);
    const int c2 = min(max((int)xf1, 0), FW - 2);
    coff[0] = c0 * C4;
    coff[1] = coff[0] + C4;
    coff[2] = c2 * C4;
    coff[3] = coff[2] + C4;
}

template <int NR>
__device__ __forceinline__ void do_row_far(
    const float4* __restrict__ prow, float4* __restrict__ orow,
    const int dr, const float xbase, const float dx,
    const float wy0, const float wy1)
{
    int roff[NR];
    roff[0] = 0;
    roff[1] = ROWS4;
    if (NR == 3) { roff[2] = 2 * ROWS4; }
    if (NR == 4) { roff[2] = dr * ROWS4; roff[3] = roff[2] + ROWS4; }

    constexpr int RB = NR - 2;

    float4 g[2][NR][4];
    float wx0[2], wx1[2];

    {
        int coff[4];
        px_cols(xbase, dx, 0, coff, wx0[0], wx1[0]);
#pragma unroll
        for (int i = 0; i < NR; i++)
#pragma unroll
            for (int j = 0; j < 4; j++)
                g[0][i][j] = prow[roff[i] + coff[j]];
    }

#pragma unroll
    for (int px = 0; px < PO; px++) {
        const int cur = px & 1;
        const int nxt = cur ^ 1;

        if (px < PO - 1) {
            int coff[4];
            px_cols(xbase, dx, px + 1, coff, wx0[nxt], wx1[nxt]);
#pragma unroll
            for (int i = 0; i < NR; i++)
#pragma unroll
                for (int j = 0; j < 4; j++)
                    g[nxt][i][j] = prow[roff[i] + coff[j]];
        }

        const float a0 = wx0[cur], a1 = wx1[cur];
        float4 m = wsum(g[cur][0][0], g[cur][0][1],
                        g[cur][1][0], g[cur][1][1], a0, wy0);
        max4(m, wsum(g[cur][0][2], g[cur][0][3],
                     g[cur][1][2], g[cur][1][3], a1, wy0));
        max4(m, wsum(g[cur][RB][0], g[cur][RB][1],
                     g[cur][RB + 1][0], g[cur][RB + 1][1], a0, wy1));
        max4(m, wsum(g[cur][RB][2], g[cur][RB][3],
                     g[cur][RB + 1][2], g[cur][RB + 1][3], a1, wy1));

        orow[px * C4] = m;
    }
}

// ---------------- NEAR path (dx < 1): 3 cols + hat weights ----------------

template <int NR>
__device__ __forceinline__ void do_row_near(
    const float4* __restrict__ prow, float4* __restrict__ orow,
    const int dr, const float xbase, const float dx,
    const float wy0, const float wy1)
{
    int roff[NR];
    roff[0] = 0;
    roff[1] = ROWS4;
    if (NR == 3) { roff[2] = 2 * ROWS4; }
    if (NR == 4) { roff[2] = dr * ROWS4; roff[3] = roff[2] + ROWS4; }

    constexpr int RB = NR - 2;

    float4 g[2][NR][3];
    float wx0b[2];
    float hw[2][3];   // hat weights for sample1 over nominal cols c0..c0+2

    auto setup = [&](const int px, const int buf) {
        const float xs0 = fmaf((float)(2 * px), dx, xbase);
        const float xs1 = xs0 + dx;
        const float xf0 = floorf(xs0);
        wx0b[buf] = xs0 - xf0;
        // Clamp never fires on in-range data; bounds accesses only.
        const int c0 = min(max((int)xf0, 0), FW - 2);
        const float cf = (float)c0;
        // Hat weights from NOMINAL column positions (exact bilinear weights).
        hw[buf][0] = fmaxf(0.0f, 1.0f - fabsf(xs1 - cf));
        hw[buf][1] = fmaxf(0.0f, 1.0f - fabsf(xs1 - (cf + 1.0f)));
        hw[buf][2] = fmaxf(0.0f, 1.0f - fabsf(xs1 - (cf + 2.0f)));
        // Loads from CLAMPED columns (weight is 0 whenever clamp engages).
        const int off2 = (min(c0 + 2, FW - 1) - c0) * C4;
        const float4* pc = prow + c0 * C4;
#pragma unroll
        for (int i = 0; i < NR; i++) {
            g[buf][i][0] = pc[roff[i]];
            g[buf][i][1] = pc[roff[i] + C4];
            g[buf][i][2] = pc[roff[i] + off2];
        }
    };

    setup(0, 0);

#pragma unroll
    for (int px = 0; px < PO; px++) {
        const int cur = px & 1;
        const int nxt = cur ^ 1;

        if (px < PO - 1) setup(px + 1, nxt);

        const float a0  = wx0b[cur];
        const float aa0 = 1.0f - a0;
        const float h0 = hw[cur][0], h1 = hw[cur][1], h2 = hw[cur][2];

        float4 m;
        bool first = true;
#pragma unroll
        for (int band = 0; band < 2; band++) {
            const int   rt = band ? RB  : 0;
            const float b  = band ? wy1 : wy0;
            const float bb = 1.0f - b;

            // Shared row-lerp per column, feeds both x-samples.
            float4 rm[3];
#pragma unroll
            for (int j = 0; j < 3; j++) {
                const float4 t = g[cur][rt][j];
                const float4 u = g[cur][rt + 1][j];
                rm[j].x = fmaf(u.x, b, t.x * bb);
                rm[j].y = fmaf(u.y, b, t.y * bb);
                rm[j].z = fmaf(u.z, b, t.z * bb);
                rm[j].w = fmaf(u.w, b, t.w * bb);
            }

            // sample0: cols (0,1) with weights (1-wx0, wx0).
            float4 s0;
            s0.x = fmaf(rm[1].x, a0, rm[0].x * aa0);
            s0.y = fmaf(rm[1].y, a0, rm[0].y * aa0);
            s0.z = fmaf(rm[1].z, a0, rm[0].z * aa0);
            s0.w = fmaf(rm[1].w, a0, rm[0].w * aa0);

            // sample1: hat-weighted sum over all 3 cols (true corners get
            // (1-wx1, wx1); third col weight is exactly 0).
            float4 s1;
            s1.x = fmaf(rm[2].x, h2, fmaf(rm[1].x, h1, rm[0].x * h0));
            s1.y = fmaf(rm[2].y, h2, fmaf(rm[1].y, h1, rm[0].y * h0));
            s1.z = fmaf(rm[2].z, h2, fmaf(rm[1].z, h1, rm[0].z * h0));
            s1.w = fmaf(rm[2].w, h2, fmaf(rm[1].w, h1, rm[0].w * h0));

            if (first) { m = s0; first = false; }
            else       { max4(m, s0); }
            max4(m, s1);
        }

        orow[px * C4] = m;
    }
}

__global__ __launch_bounds__(TPB, 4)
void roi_pool_kernel(const float* __restrict__ feat,
                     const float* __restrict__ boxes,
                     float* __restrict__ out)
{
    const int bid  = blockIdx.x;           // 0 .. 4200
    const int n    = bid / (PO * 2);       // box
    const int rem  = bid - n * (PO * 2);
    const int py   = rem >> 1;             // pooled row
    const int c4   = (rem & 1) * TPB + threadIdx.x;

    const float4 box = ((const float4*)boxes)[n];

    const float scale = 1.0f / (float)(CROP - 1);
    const float dy = (box.z - box.x) * (float)(FH - 1) * scale;
    const float dx = (box.w - box.y) * (float)(FW - 1) * scale;
    const float xbase = box.y * (float)(FW - 1);

    const float ys0 = fmaf((float)(2 * py), dy, box.x * (float)(FH - 1));
    const float ys1 = ys0 + dy;
    const float yf0 = floorf(ys0), yf1 = floorf(ys1);
    const float wy0 = ys0 - yf0, wy1 = ys1 - yf1;

    // Clamps never fire on in-range data (coords in [0,49)).
    const int r0 = min(max((int)yf0, 0), FH - 2);
    const int r2 = min(max((int)yf1, 0), FH - 2);
    const int dr = r2 - r0;

    const float4* __restrict__ prow = (const float4*)feat + (r0 * ROWS4 + c4);
    float4* __restrict__ orow =
        (float4*)out + ((n * PO + py) * PO * C4 + c4);

    const int nrCase = (dr == 0) ? 0 : ((dr == 1) ? 1 : 2);

    if (dx < 1.0f) {
        if (nrCase == 0)      do_row_near<2>(prow, orow, dr, xbase, dx, wy0, wy1);
        else if (nrCase == 1) do_row_near<3>(prow, orow, dr, xbase, dx, wy0, wy1);
        else                  do_row_near<4>(prow, orow, dr, xbase, dx, wy0, wy1);
    } else {
        if (nrCase == 0)      do_row_far<2>(prow, orow, dr, xbase, dx, wy0, wy1);
        else if (nrCase == 1) do_row_far<3>(prow, orow, dr, xbase, dx, wy0, wy1);
        else                  do_row_far<4>(prow, orow, dr, xbase, dx, wy0, wy1);
    }
}

extern "C" void kernel_launch(void* const* d_in, const int* in_sizes, int n_in,
                              void* d_out, int out_size)
{
    const float* feat  = (const float*)d_in[0];
    const float* boxes = (const float*)d_in[1];
    float* out = (float*)d_out;

    roi_pool_kernel<<<NBOX * PO * 2, TPB>>>(feat, boxes, out);
}

// round 15
// speedup vs baseline: 1.1848x; 1.1848x over previous
#include <cuda_runtime.h>
#include <math.h>

// features: (1, 50, 50, 1024) fp32 NHWC ; boxes: (1, 300, 4) fp32 [y1,x1,y2,x2]
// crop 14x14 bilinear, 2x2 max pool -> out (1, 300, 7, 7, 1024) fp32
// Block = (box, pooled-row py, channel-half). 128 threads, 1 float4 group each.
// Branchless 4-column pattern per px; rows hoisted per block (NR=2/3/4).
// Depth-2 px pipeline keeps ~16 loads/warp in flight (proven R10 structure).
// Micro-polish: incremental x coordinate, marched output pointer.

#define FH 50
#define FW 50
#define FC 1024
#define NBOX 300
#define CROP 14
#define PO 7
#define C4 (FC / 4)      // 256 float4 channel groups
#define TPB 128
#define ROWS4 (FW * C4)

__device__ __forceinline__ float4 wsum(const float4 tl, const float4 tr,
                                       const float4 bl, const float4 br,
                                       const float a, const float b)
{
    const float aa = 1.0f - a;
    const float bb = 1.0f - b;
    const float w0 = aa * bb, w1 = a * bb, w2 = aa * b, w3 = a * b;
    float4 v;
    v.x = fmaf(w3, br.x, fmaf(w2, bl.x, fmaf(w1, tr.x, w0 * tl.x)));
    v.y = fmaf(w3, br.y, fmaf(w2, bl.y, fmaf(w1, tr.y, w0 * tl.y)));
    v.z = fmaf(w3, br.z, fmaf(w2, bl.z, fmaf(w1, tr.z, w0 * tl.z)));
    v.w = fmaf(w3, br.w, fmaf(w2, bl.w, fmaf(w1, tr.w, w0 * tl.w)));
    return v;
}

__device__ __forceinline__ void max4(float4& m, const float4 v)
{
    m.x = fmaxf(m.x, v.x);
    m.y = fmaxf(m.y, v.y);
    m.z = fmaxf(m.z, v.z);
    m.w = fmaxf(m.w, v.w);
}

// Column offsets (float4 units) for sample pair at xs0 (incremental form).
__device__ __forceinline__ void px_cols(const float xs0, const float dx,
                                        int coff[4], float& wx0, float& wx1)
{
    const float xs1 = xs0 + dx;
    const float xf0 = floorf(xs0), xf1 = floorf(xs1);
    wx0 = xs0 - xf0;
    wx1 = xs1 - xf1;
    // Clamps never fire on in-range data; they only bound memory accesses.
    const int c0 = min(max((int)xf0, 0), FW - 2);
    const int c2 = min(max((int)xf1, 0), FW - 2);
    coff[0] = c0 * C4;
    coff[1] = coff[0] + C4;
    coff[2] = c2 * C4;
    coff[3] = coff[2] + C4;
}

// NR = distinct rows (2: same pair; 3: chain; 4: two pairs at distance dr).
// Top samples use rows (0,1); bottom samples use rows (NR-2, NR-1).
template <int NR>
__device__ __forceinline__ void do_row(
    const float4* __restrict__ prow,  // f4 + r0*ROWS4 + c4
    float4* __restrict__ orow,        // out + (box*49 + py*7)*C4 + c4
    const int dr,
    const float xbase, const float dx,
    const float wy0, const float wy1)
{
    int roff[NR];
    roff[0] = 0;
    roff[1] = ROWS4;
    if (NR == 3) { roff[2] = 2 * ROWS4; }
    if (NR == 4) { roff[2] = dr * ROWS4; roff[3] = roff[2] + ROWS4; }

    constexpr int RB = NR - 2;
    const float step = dx + dx;

    float4 g[2][NR][4];
    float wx0[2], wx1[2];

    // Prologue: issue px=0 loads.
    float xs_next = xbase;
    {
        int coff[4];
        px_cols(xs_next, dx, coff, wx0[0], wx1[0]);
#pragma unroll
        for (int i = 0; i < NR; i++)
#pragma unroll
            for (int j = 0; j < 4; j++)
                g[0][i][j] = prow[roff[i] + coff[j]];
    }

    float4* optr = orow;

#pragma unroll
    for (int px = 0; px < PO; px++) {
        const int cur = px & 1;
        const int nxt = cur ^ 1;

        // Issue px+1's loads BEFORE consuming px's data.
        if (px < PO - 1) {
            xs_next += step;
            int coff[4];
            px_cols(xs_next, dx, coff, wx0[nxt], wx1[nxt]);
#pragma unroll
            for (int i = 0; i < NR; i++)
#pragma unroll
                for (int j = 0; j < 4; j++)
                    g[nxt][i][j] = prow[roff[i] + coff[j]];
        }

        // Compute px from the current buffer.
        const float a0 = wx0[cur], a1 = wx1[cur];
        float4 m = wsum(g[cur][0][0], g[cur][0][1],
                        g[cur][1][0], g[cur][1][1], a0, wy0);
        max4(m, wsum(g[cur][0][2], g[cur][0][3],
                     g[cur][1][2], g[cur][1][3], a1, wy0));
        max4(m, wsum(g[cur][RB][0], g[cur][RB][1],
                     g[cur][RB + 1][0], g[cur][RB + 1][1], a0, wy1));
        max4(m, wsum(g[cur][RB][2], g[cur][RB][3],
                     g[cur][RB + 1][2], g[cur][RB + 1][3], a1, wy1));

        *optr = m;
        optr += C4;
    }
}

__global__ __launch_bounds__(TPB, 4)
void roi_pool_kernel(const float* __restrict__ feat,
                     const float* __restrict__ boxes,
                     float* __restrict__ out)
{
    const int bid  = blockIdx.x;           // 0 .. 4200
    const int n    = bid / (PO * 2);       // box
    const int rem  = bid - n * (PO * 2);
    const int py   = rem >> 1;             // pooled row
    const int c4   = (rem & 1) * TPB + threadIdx.x;

    const float4 box = __ldg(((const float4*)boxes) + n);

    const float scale = 1.0f / (float)(CROP - 1);
    const float dy = (box.z - box.x) * (float)(FH - 1) * scale;
    const float dx = (box.w - box.y) * (float)(FW - 1) * scale;
    const float xbase = box.y * (float)(FW - 1);

    const float ys0 = fmaf((float)(2 * py), dy, box.x * (float)(FH - 1));
    const float ys1 = ys0 + dy;
    const float yf0 = floorf(ys0), yf1 = floorf(ys1);
    const float wy0 = ys0 - yf0, wy1 = ys1 - yf1;

    // Clamps never fire on in-range data (coords in [0,49)).
    const int r0 = min(max((int)yf0, 0), FH - 2);
    const int r2 = min(max((int)yf1, 0), FH - 2);
    const int dr = r2 - r0;

    const float4* __restrict__ prow = (const float4*)feat + (r0 * ROWS4 + c4);
    float4* __restrict__ orow =
        (float4*)out + ((n * PO + py) * PO * C4 + c4);

    if (dr == 0)      do_row<2>(prow, orow, dr, xbase, dx, wy0, wy1);
    else if (dr == 1) do_row<3>(prow, orow, dr, xbase, dx, wy0, wy1);
    else              do_row<4>(prow, orow, dr, xbase, dx, wy0, wy1);
}

extern "C" void kernel_launch(void* const* d_in, const int* in_sizes, int n_in,
                              void* d_out, int out_size)
{
    const float* feat  = (const float*)d_in[0];
    const float* boxes = (const float*)d_in[1];
    float* out = (float*)d_out;

    roi_pool_kernel<<<NBOX * PO * 2, TPB>>>(feat, boxes, out);
}